// round 10
// baseline (speedup 1.0000x reference)
#include <cuda_runtime.h>
#include <math_constants.h>

#define BATCH 2
#define N1 4096
#define N2 32768
#define C1 128
#define C2 64
#define F1 128
#define F2 128
#define IN0S 131   // 3 + C1
#define IN1S 67    // 3 + C2
#define KEPS 1e-7f

#define AST 68     // sA row stride (mod 32 = 4 -> conflict-free, mult of 4)
#define HST 136    // sH row stride (mod 32 = 8 -> conflict-free, mult of 4)

#define NSLICE 8               // candidate-dim split
#define CPT (N1 / NSLICE)      // 512 candidates per slice

// Scratch (static device globals: allocation-free)
__device__ float g_PW[BATCH * N1 * F1];          // points1 @ W1[0:128,:]
__device__ int   g_idx[BATCH * N2 * 3];
__device__ float g_w[BATCH * N2 * 3];
__device__ float g_pd[BATCH * N2 * NSLICE * 3];  // partial top-3 dists (shifted)
__device__ int   g_pi[BATCH * N2 * NSLICE * 3];  // partial top-3 indices

// ---------------------------------------------------------------------------
// K0: PW[b,j,f] = sum_c points1[b,j,c] * W1[c,f]   (rows 0..127 of W1)
// ---------------------------------------------------------------------------
__global__ void pw_kernel(const float* __restrict__ in0, const float* __restrict__ W1) {
    __shared__ float srow[8][128];
    int tid = threadIdx.x;
    long rowbase = (long)blockIdx.x * 8;
    #pragma unroll
    for (int r = 0; r < 8; r++)
        srow[r][tid] = in0[(rowbase + r) * IN0S + 3 + tid];
    __syncthreads();
    float acc[8];
    #pragma unroll
    for (int r = 0; r < 8; r++) acc[r] = 0.f;
    #pragma unroll 4
    for (int k = 0; k < 128; k++) {
        float w = __ldg(&W1[k * F1 + tid]);
        #pragma unroll
        for (int r = 0; r < 8; r++) acc[r] = fmaf(srow[r][k], w, acc[r]);
    }
    #pragma unroll
    for (int r = 0; r < 8; r++)
        g_PW[(rowbase + r) * F1 + tid] = acc[r];
}

// ---------------------------------------------------------------------------
// K1a: partial 3-NN. Each block: 1024 queries (4 per thread) x CPT candidates.
// Shifted-space distance |p|^2 - 2 p.q : 3 FFMA + 1 cmp per cand per query.
// grid = (N2/1024, NSLICE, BATCH)
// ---------------------------------------------------------------------------
#define TOP3_UPDATE(d, e0, e1, e2, i0, i1, i2, j)              \
    if ((d) < (e2)) {                                          \
        if ((d) < (e1)) {                                      \
            (e2) = (e1); (i2) = (i1);                          \
            if ((d) < (e0)) { (e1) = (e0); (i1) = (i0);        \
                              (e0) = (d);  (i0) = (j); }       \
            else            { (e1) = (d);  (i1) = (j); }       \
        } else { (e2) = (d); (i2) = (j); }                     \
    }

__global__ void knn_part_kernel(const float* __restrict__ in0,
                                const float* __restrict__ in1) {
    __shared__ float4 tile[CPT];
    int tid = threadIdx.x;
    int b  = blockIdx.z;
    int sl = blockIdx.y;
    int cs = sl * CPT;                       // candidate slice start
    int q0 = blockIdx.x * 1024 + tid;        // queries q0, q0+256, q0+512, q0+768

    float qx[4], qy[4], qz[4], nx[4], ny[4], nz[4];
    #pragma unroll
    for (int v = 0; v < 4; v++) {
        const float* q = in1 + (size_t)(b * N2 + q0 + v * 256) * IN1S;
        qx[v] = q[0]; qy[v] = q[1]; qz[v] = q[2];
        nx[v] = -2.f * qx[v]; ny[v] = -2.f * qy[v]; nz[v] = -2.f * qz[v];
    }

    // fill tile
    for (int s = tid; s < CPT; s += 256) {
        const float* p = in0 + (size_t)(b * N1 + cs + s) * IN0S;
        float px = p[0], py = p[1], pz = p[2];
        tile[s] = make_float4(px, py, pz, fmaf(px, px, fmaf(py, py, pz * pz)));
    }
    __syncthreads();

    float e0[4], e1[4], e2[4];
    int   i0[4], i1[4], i2[4];
    #pragma unroll
    for (int v = 0; v < 4; v++) {
        e0[v] = CUDART_INF_F; e1[v] = CUDART_INF_F; e2[v] = CUDART_INF_F;
        i0[v] = 0; i1[v] = 0; i2[v] = 0;
    }

    #pragma unroll 4
    for (int s = 0; s < CPT; s++) {
        float4 p = tile[s];
        int j = cs + s;
        #pragma unroll
        for (int v = 0; v < 4; v++) {
            float d = fmaf(p.x, nx[v], p.w);
            d = fmaf(p.y, ny[v], d);
            d = fmaf(p.z, nz[v], d);
            TOP3_UPDATE(d, e0[v], e1[v], e2[v], i0[v], i1[v], i2[v], j);
        }
    }

    #pragma unroll
    for (int v = 0; v < 4; v++) {
        size_t o = ((size_t)(b * N2 + q0 + v * 256) * NSLICE + sl) * 3;
        g_pd[o + 0] = e0[v]; g_pd[o + 1] = e1[v]; g_pd[o + 2] = e2[v];
        g_pi[o + 0] = i0[v]; g_pi[o + 1] = i1[v]; g_pi[o + 2] = i2[v];
    }
}

// ---------------------------------------------------------------------------
// K1b: merge NSLICE partial top-3s per query (slice order + strict < keeps
// lowest-index tie-break identical to a sequential scan), exact-distance
// recompute for the winners, weights + xyz output.
// ---------------------------------------------------------------------------
__global__ void knn_merge_kernel(const float* __restrict__ in0,
                                 const float* __restrict__ in1,
                                 float* __restrict__ out_xyz, int write_xyz) {
    int g = blockIdx.x * 256 + threadIdx.x;   // global query in [0, BATCH*N2)
    int b = g / N2;

    float e0 = CUDART_INF_F, e1 = CUDART_INF_F, e2 = CUDART_INF_F;
    int i0 = 0, i1 = 0, i2 = 0;
    size_t base = (size_t)g * NSLICE * 3;
    #pragma unroll
    for (int t = 0; t < NSLICE * 3; t++) {
        float d = g_pd[base + t];
        int   j = g_pi[base + t];
        TOP3_UPDATE(d, e0, e1, e2, i0, i1, i2, j);
    }

    const float* q = in1 + (size_t)g * IN1S;
    float qx = q[0], qy = q[1], qz = q[2];

    const float* P = in0 + (size_t)(b * N1) * IN0S;
    const float* p = P + (size_t)i0 * IN0S;
    float dx = p[0] - qx, dy = p[1] - qy, dz = p[2] - qz;
    float d0 = fmaxf(fmaf(dx, dx, fmaf(dy, dy, dz * dz)), KEPS);
    p = P + (size_t)i1 * IN0S;
    dx = p[0] - qx; dy = p[1] - qy; dz = p[2] - qz;
    float d1 = fmaxf(fmaf(dx, dx, fmaf(dy, dy, dz * dz)), KEPS);
    p = P + (size_t)i2 * IN0S;
    dx = p[0] - qx; dy = p[1] - qy; dz = p[2] - qz;
    float d2 = fmaxf(fmaf(dx, dx, fmaf(dy, dy, dz * dz)), KEPS);

    float w0 = 1.f / d0, w1 = 1.f / d1, w2 = 1.f / d2;
    float inv = 1.f / (w0 + w1 + w2);
    g_idx[g * 3 + 0] = i0; g_idx[g * 3 + 1] = i1; g_idx[g * 3 + 2] = i2;
    g_w[g * 3 + 0] = w0 * inv; g_w[g * 3 + 1] = w1 * inv; g_w[g * 3 + 2] = w2 * inv;
    if (write_xyz) {
        out_xyz[(size_t)g * 3 + 0] = qx;
        out_xyz[(size_t)g * 3 + 1] = qy;
        out_xyz[(size_t)g * 3 + 2] = qz;
    }
}

// ---------------------------------------------------------------------------
// K2: fused MLP v3. 128-query tile, 512 threads, 4x8 register sub-tiles.
// Thread (ty,tx): ty=tid>>4 (0..31), tx=tid&15; rows ty+32*i, cols tx*8..+7.
// 16 warps/SM (4 per SMSP) for latency hiding; 1 CTA/SM (204KB smem).
// ---------------------------------------------------------------------------
__global__ void mlp_kernel(const float* __restrict__ in1, const float* __restrict__ W1,
                           const float* __restrict__ b1, const float* __restrict__ W2,
                           const float* __restrict__ b2, float* __restrict__ out) {
    extern __shared__ float sm[];
    float* sW2  = sm;                 // 16384
    float* sW1b = sW2 + 16384;        //  8192
    float* sA   = sW1b + 8192;        //  128*AST
    float* sH   = sA + 128 * AST;     //  128*HST
    float* sB1  = sH + 128 * HST;     //   128
    float* sB2  = sB1 + 128;          //   128

    int tid = threadIdx.x;
    int g0 = blockIdx.x * 128;
    int bb = g0 / N2;

    for (int i = tid; i < 16384; i += 512) sW2[i] = W2[i];
    for (int i = tid; i < 8192;  i += 512) sW1b[i] = W1[C1 * F1 + i];
    if (tid < 128) { sB1[tid] = b1[tid]; sB2[tid] = b2[tid]; }
    for (int i = tid; i < 128 * 64; i += 512) {
        int m = i >> 6, c = i & 63;
        sA[m * AST + c] = in1[(size_t)(g0 + m) * IN1S + 3 + c];
    }
    __syncthreads();

    // Gather interpolation in projected space -> sH (4 threads per query row)
    {
        int m  = tid >> 2;             // query row 0..127
        int fo = (tid & 3) * 32;       // feature quarter
        int g  = g0 + m;
        int j0 = g_idx[g * 3 + 0], j1 = g_idx[g * 3 + 1], j2 = g_idx[g * 3 + 2];
        float w0 = g_w[g * 3 + 0], w1 = g_w[g * 3 + 1], w2 = g_w[g * 3 + 2];
        const float* Pg = g_PW + (size_t)bb * N1 * F1;
        const float* p0 = Pg + (size_t)j0 * F1;
        const float* p1 = Pg + (size_t)j1 * F1;
        const float* p2 = Pg + (size_t)j2 * F1;
        #pragma unroll
        for (int u = 0; u < 32; u += 4) {
            int f = fo + u;
            float4 a  = *(const float4*)(p0 + f);
            float4 c4 = *(const float4*)(p1 + f);
            float4 e4 = *(const float4*)(p2 + f);
            float4 bv = *(const float4*)(sB1 + f);
            float4 r;
            r.x = bv.x + w0 * a.x + w1 * c4.x + w2 * e4.x;
            r.y = bv.y + w0 * a.y + w1 * c4.y + w2 * e4.y;
            r.z = bv.z + w0 * a.z + w1 * c4.z + w2 * e4.z;
            r.w = bv.w + w0 * a.w + w1 * c4.w + w2 * e4.w;
            *(float4*)(sH + m * HST + f) = r;
        }
    }
    __syncthreads();

    int ty = tid >> 4, tx = tid & 15;
    int nn = tx * 8;

    // init accumulators from gathered interp (+b1) in sH
    float acc[4][8];
    #pragma unroll
    for (int i = 0; i < 4; i++) {
        int r = ty + 32 * i;
        float4 v0 = *(const float4*)(sH + r * HST + nn);
        float4 v1 = *(const float4*)(sH + r * HST + nn + 4);
        acc[i][0] = v0.x; acc[i][1] = v0.y; acc[i][2] = v0.z; acc[i][3] = v0.w;
        acc[i][4] = v1.x; acc[i][5] = v1.y; acc[i][6] = v1.z; acc[i][7] = v1.w;
    }

    // GEMM1: A(128x64) @ W1b(64x128)
    #pragma unroll 4
    for (int k = 0; k < 64; k++) {
        float4 w0 = *(const float4*)(sW1b + k * 128 + nn);
        float4 w1 = *(const float4*)(sW1b + k * 128 + nn + 4);
        #pragma unroll
        for (int i = 0; i < 4; i++) {
            float a = sA[(ty + 32 * i) * AST + k];
            acc[i][0] = fmaf(a, w0.x, acc[i][0]);
            acc[i][1] = fmaf(a, w0.y, acc[i][1]);
            acc[i][2] = fmaf(a, w0.z, acc[i][2]);
            acc[i][3] = fmaf(a, w0.w, acc[i][3]);
            acc[i][4] = fmaf(a, w1.x, acc[i][4]);
            acc[i][5] = fmaf(a, w1.y, acc[i][5]);
            acc[i][6] = fmaf(a, w1.z, acc[i][6]);
            acc[i][7] = fmaf(a, w1.w, acc[i][7]);
        }
    }

    // relu -> sH (same cells this thread read/initialized: race-free)
    #pragma unroll
    for (int i = 0; i < 4; i++) {
        int r = ty + 32 * i;
        float4 v0, v1;
        v0.x = fmaxf(acc[i][0], 0.f); v0.y = fmaxf(acc[i][1], 0.f);
        v0.z = fmaxf(acc[i][2], 0.f); v0.w = fmaxf(acc[i][3], 0.f);
        v1.x = fmaxf(acc[i][4], 0.f); v1.y = fmaxf(acc[i][5], 0.f);
        v1.z = fmaxf(acc[i][6], 0.f); v1.w = fmaxf(acc[i][7], 0.f);
        *(float4*)(sH + r * HST + nn) = v0;
        *(float4*)(sH + r * HST + nn + 4) = v1;
    }
    __syncthreads();

    // GEMM2: H(128x128) @ W2(128x128)
    float4 b2a = *(const float4*)(sB2 + nn);
    float4 b2b = *(const float4*)(sB2 + nn + 4);
    float acc2[4][8];
    #pragma unroll
    for (int i = 0; i < 4; i++) {
        acc2[i][0] = b2a.x; acc2[i][1] = b2a.y; acc2[i][2] = b2a.z; acc2[i][3] = b2a.w;
        acc2[i][4] = b2b.x; acc2[i][5] = b2b.y; acc2[i][6] = b2b.z; acc2[i][7] = b2b.w;
    }
    #pragma unroll 4
    for (int k = 0; k < 128; k++) {
        float4 w0 = *(const float4*)(sW2 + k * 128 + nn);
        float4 w1 = *(const float4*)(sW2 + k * 128 + nn + 4);
        #pragma unroll
        for (int i = 0; i < 4; i++) {
            float h = sH[(ty + 32 * i) * HST + k];
            acc2[i][0] = fmaf(h, w0.x, acc2[i][0]);
            acc2[i][1] = fmaf(h, w0.y, acc2[i][1]);
            acc2[i][2] = fmaf(h, w0.z, acc2[i][2]);
            acc2[i][3] = fmaf(h, w0.w, acc2[i][3]);
            acc2[i][4] = fmaf(h, w1.x, acc2[i][4]);
            acc2[i][5] = fmaf(h, w1.y, acc2[i][5]);
            acc2[i][6] = fmaf(h, w1.z, acc2[i][6]);
            acc2[i][7] = fmaf(h, w1.w, acc2[i][7]);
        }
    }

    // relu -> global
    #pragma unroll
    for (int i = 0; i < 4; i++) {
        int g = g0 + ty + 32 * i;
        float4 v0, v1;
        v0.x = fmaxf(acc2[i][0], 0.f); v0.y = fmaxf(acc2[i][1], 0.f);
        v0.z = fmaxf(acc2[i][2], 0.f); v0.w = fmaxf(acc2[i][3], 0.f);
        v1.x = fmaxf(acc2[i][4], 0.f); v1.y = fmaxf(acc2[i][5], 0.f);
        v1.z = fmaxf(acc2[i][6], 0.f); v1.w = fmaxf(acc2[i][7], 0.f);
        *(float4*)(out + (size_t)g * F2 + nn) = v0;
        *(float4*)(out + (size_t)g * F2 + nn + 4) = v1;
    }
}

// ---------------------------------------------------------------------------
extern "C" void kernel_launch(void* const* d_in, const int* in_sizes, int n_in,
                              void* d_out, int out_size) {
    const float* in0 = (const float*)d_in[0];   // inputs0 (B, N1, 131)
    const float* in1 = (const float*)d_in[1];   // inputs1 (B, N2, 67)
    const float* W1  = (const float*)d_in[2];   // (192, 128)
    const float* b1  = (const float*)d_in[3];   // (128,)
    const float* W2  = (const float*)d_in[4];   // (128, 128)
    const float* b2  = (const float*)d_in[5];   // (128,)
    float* out = (float*)d_out;

    const int x_elems = BATCH * N2 * F2;                 // 8,388,608
    int write_xyz = (out_size >= x_elems + BATCH * N2 * 3) ? 1 : 0;

    const int mlp_smem = (16384 + 8192 + 128 * AST + 128 * HST + 256) * (int)sizeof(float);
    cudaFuncSetAttribute(mlp_kernel, cudaFuncAttributeMaxDynamicSharedMemorySize, mlp_smem);

    knn_part_kernel<<<dim3(N2 / 1024, NSLICE, BATCH), 256>>>(in0, in1);
    pw_kernel<<<(BATCH * N1) / 8, 128>>>(in0, W1);
    knn_merge_kernel<<<(BATCH * N2) / 256, 256>>>(in0, in1, out + x_elems, write_xyz);
    mlp_kernel<<<(BATCH * N2) / 128, 512, mlp_smem>>>(in1, W1, b1, W2, b2, out);
}

// round 14
// speedup vs baseline: 1.8591x; 1.8591x over previous
#include <cuda_runtime.h>
#include <math_constants.h>

#define BATCH 2
#define N1 4096
#define N2 32768
#define C1 128
#define C2 64
#define F1 128
#define F2 128
#define IN0S 131   // 3 + C1
#define IN1S 67    // 3 + C2
#define KEPS 1e-7f

#define AST 68     // sA row stride (mod 32 = 4 -> conflict-free, mult of 4)
#define HST 136    // sH row stride (mod 32 = 8 -> conflict-free, mult of 4)

#define NSLICE 4               // candidate-dim split
#define CPT (N1 / NSLICE)      // 1024 candidates per slice

// Scratch (static device globals: allocation-free)
__device__ float g_PW[BATCH * N1 * F1];          // points1 @ W1[0:128,:]
__device__ int   g_idx[BATCH * N2 * 3];
__device__ float g_w[BATCH * N2 * 3];
__device__ float g_pd[BATCH * N2 * NSLICE * 3];  // partial top-3 dists (shifted)
__device__ int   g_pi[BATCH * N2 * NSLICE * 3];  // partial top-3 indices

#define TOP3_UPDATE(d, e0, e1, e2, i0, i1, i2, j)              \
    if ((d) < (e2)) {                                          \
        if ((d) < (e1)) {                                      \
            (e2) = (e1); (i2) = (i1);                          \
            if ((d) < (e0)) { (e1) = (e0); (i1) = (i0);        \
                              (e0) = (d);  (i0) = (j); }       \
            else            { (e1) = (d);  (i1) = (j); }       \
        } else { (e2) = (d); (i2) = (j); }                     \
    }

// ---------------------------------------------------------------------------
// K0: PW[b,j,f] = sum_c points1[b,j,c] * W1[c,f]   (rows 0..127 of W1)
// ---------------------------------------------------------------------------
__global__ void pw_kernel(const float* __restrict__ in0, const float* __restrict__ W1) {
    __shared__ float srow[8][128];
    int tid = threadIdx.x;
    long rowbase = (long)blockIdx.x * 8;
    #pragma unroll
    for (int r = 0; r < 8; r++)
        srow[r][tid] = in0[(rowbase + r) * IN0S + 3 + tid];
    __syncthreads();
    float acc[8];
    #pragma unroll
    for (int r = 0; r < 8; r++) acc[r] = 0.f;
    #pragma unroll 4
    for (int k = 0; k < 128; k++) {
        float w = __ldg(&W1[k * F1 + tid]);
        #pragma unroll
        for (int r = 0; r < 8; r++) acc[r] = fmaf(srow[r][k], w, acc[r]);
    }
    #pragma unroll
    for (int r = 0; r < 8; r++)
        g_PW[(rowbase + r) * F1 + tid] = acc[r];
}

// ---------------------------------------------------------------------------
// K1a: partial 3-NN (R9 proven config). Block: 512 queries (2/thread) x 1024
// candidates. grid = (N2/512, NSLICE, BATCH)
// ---------------------------------------------------------------------------
__global__ void knn_part_kernel(const float* __restrict__ in0,
                                const float* __restrict__ in1) {
    __shared__ float4 tile[CPT];
    int tid = threadIdx.x;
    int b  = blockIdx.z;
    int sl = blockIdx.y;
    int cs = sl * CPT;
    int qA = blockIdx.x * 512 + tid;
    int qB = qA + 256;
    int gA = b * N2 + qA;
    int gB = b * N2 + qB;

    const float* q = in1 + (size_t)gA * IN1S;
    float nAx = -2.f * q[0], nAy = -2.f * q[1], nAz = -2.f * q[2];
    q = in1 + (size_t)gB * IN1S;
    float nBx = -2.f * q[0], nBy = -2.f * q[1], nBz = -2.f * q[2];

    for (int s = tid; s < CPT; s += 256) {
        const float* p = in0 + (size_t)(b * N1 + cs + s) * IN0S;
        float px = p[0], py = p[1], pz = p[2];
        tile[s] = make_float4(px, py, pz, fmaf(px, px, fmaf(py, py, pz * pz)));
    }
    __syncthreads();

    float eA0 = CUDART_INF_F, eA1 = CUDART_INF_F, eA2 = CUDART_INF_F;
    float eB0 = CUDART_INF_F, eB1 = CUDART_INF_F, eB2 = CUDART_INF_F;
    int iA0 = 0, iA1 = 0, iA2 = 0, iB0 = 0, iB1 = 0, iB2 = 0;

    #pragma unroll 8
    for (int s = 0; s < CPT; s++) {
        float4 p = tile[s];
        float dA = fmaf(p.x, nAx, p.w);
        dA = fmaf(p.y, nAy, dA);
        dA = fmaf(p.z, nAz, dA);
        float dB = fmaf(p.x, nBx, p.w);
        dB = fmaf(p.y, nBy, dB);
        dB = fmaf(p.z, nBz, dB);
        int j = cs + s;
        TOP3_UPDATE(dA, eA0, eA1, eA2, iA0, iA1, iA2, j);
        TOP3_UPDATE(dB, eB0, eB1, eB2, iB0, iB1, iB2, j);
    }

    size_t oA = ((size_t)gA * NSLICE + sl) * 3;
    size_t oB = ((size_t)gB * NSLICE + sl) * 3;
    g_pd[oA + 0] = eA0; g_pd[oA + 1] = eA1; g_pd[oA + 2] = eA2;
    g_pi[oA + 0] = iA0; g_pi[oA + 1] = iA1; g_pi[oA + 2] = iA2;
    g_pd[oB + 0] = eB0; g_pd[oB + 1] = eB1; g_pd[oB + 2] = eB2;
    g_pi[oB + 0] = iB0; g_pi[oB + 1] = iB1; g_pi[oB + 2] = iB2;
}

// ---------------------------------------------------------------------------
// K1b: merge partials (slice order + strict < == sequential tie-break),
// exact-distance recompute, weights + xyz.
// ---------------------------------------------------------------------------
__global__ void knn_merge_kernel(const float* __restrict__ in0,
                                 const float* __restrict__ in1,
                                 float* __restrict__ out_xyz, int write_xyz) {
    int g = blockIdx.x * 256 + threadIdx.x;
    int b = g / N2;

    float e0 = CUDART_INF_F, e1 = CUDART_INF_F, e2 = CUDART_INF_F;
    int i0 = 0, i1 = 0, i2 = 0;
    size_t base = (size_t)g * NSLICE * 3;
    #pragma unroll
    for (int t = 0; t < NSLICE * 3; t++) {
        float d = g_pd[base + t];
        int   j = g_pi[base + t];
        TOP3_UPDATE(d, e0, e1, e2, i0, i1, i2, j);
    }

    const float* q = in1 + (size_t)g * IN1S;
    float qx = q[0], qy = q[1], qz = q[2];

    const float* P = in0 + (size_t)(b * N1) * IN0S;
    const float* p = P + (size_t)i0 * IN0S;
    float dx = p[0] - qx, dy = p[1] - qy, dz = p[2] - qz;
    float d0 = fmaxf(fmaf(dx, dx, fmaf(dy, dy, dz * dz)), KEPS);
    p = P + (size_t)i1 * IN0S;
    dx = p[0] - qx; dy = p[1] - qy; dz = p[2] - qz;
    float d1 = fmaxf(fmaf(dx, dx, fmaf(dy, dy, dz * dz)), KEPS);
    p = P + (size_t)i2 * IN0S;
    dx = p[0] - qx; dy = p[1] - qy; dz = p[2] - qz;
    float d2 = fmaxf(fmaf(dx, dx, fmaf(dy, dy, dz * dz)), KEPS);

    float w0 = 1.f / d0, w1 = 1.f / d1, w2 = 1.f / d2;
    float inv = 1.f / (w0 + w1 + w2);
    g_idx[g * 3 + 0] = i0; g_idx[g * 3 + 1] = i1; g_idx[g * 3 + 2] = i2;
    g_w[g * 3 + 0] = w0 * inv; g_w[g * 3 + 1] = w1 * inv; g_w[g * 3 + 2] = w2 * inv;
    if (write_xyz) {
        out_xyz[(size_t)g * 3 + 0] = qx;
        out_xyz[(size_t)g * 3 + 1] = qy;
        out_xyz[(size_t)g * 3 + 2] = qz;
    }
}

// ---------------------------------------------------------------------------
// K2: fused MLP v4 = v2 (256 thr, 128-query, 8x8) + float4 k-chunk operand
// loads. Per 4 k-steps: 8 weight LDS.128 + 8 A/H LDS.128 per 256 FMA.
// ---------------------------------------------------------------------------
__global__ void __launch_bounds__(256, 1)
mlp_kernel(const float* __restrict__ in1, const float* __restrict__ W1,
           const float* __restrict__ b1, const float* __restrict__ W2,
           const float* __restrict__ b2, float* __restrict__ out) {
    extern __shared__ float sm[];
    float* sW2  = sm;                 // 16384
    float* sW1b = sW2 + 16384;        //  8192
    float* sA   = sW1b + 8192;        //  128*AST
    float* sH   = sA + 128 * AST;     //  128*HST
    float* sB1  = sH + 128 * HST;     //   128
    float* sB2  = sB1 + 128;          //   128

    int tid = threadIdx.x;
    int g0 = blockIdx.x * 128;
    int bb = g0 / N2;

    for (int i = tid; i < 16384; i += 256) sW2[i] = W2[i];
    for (int i = tid; i < 8192;  i += 256) sW1b[i] = W1[C1 * F1 + i];
    if (tid < 128) { sB1[tid] = b1[tid]; sB2[tid] = b2[tid]; }
    for (int i = tid; i < 128 * 64; i += 256) {
        int m = i >> 6, c = i & 63;
        sA[m * AST + c] = in1[(size_t)(g0 + m) * IN1S + 3 + c];
    }
    __syncthreads();

    // Gather interpolation in projected space -> sH (2 threads per query row)
    {
        int m  = tid >> 1;
        int fo = (tid & 1) * 64;
        int g  = g0 + m;
        int j0 = g_idx[g * 3 + 0], j1 = g_idx[g * 3 + 1], j2 = g_idx[g * 3 + 2];
        float w0 = g_w[g * 3 + 0], w1 = g_w[g * 3 + 1], w2 = g_w[g * 3 + 2];
        const float* Pg = g_PW + (size_t)bb * N1 * F1;
        const float* p0 = Pg + (size_t)j0 * F1;
        const float* p1 = Pg + (size_t)j1 * F1;
        const float* p2 = Pg + (size_t)j2 * F1;
        #pragma unroll
        for (int u = 0; u < 64; u += 4) {
            int f = fo + u;
            float4 a  = *(const float4*)(p0 + f);
            float4 c4 = *(const float4*)(p1 + f);
            float4 e4 = *(const float4*)(p2 + f);
            float4 bv = *(const float4*)(sB1 + f);
            float4 r;
            r.x = bv.x + w0 * a.x + w1 * c4.x + w2 * e4.x;
            r.y = bv.y + w0 * a.y + w1 * c4.y + w2 * e4.y;
            r.z = bv.z + w0 * a.z + w1 * c4.z + w2 * e4.z;
            r.w = bv.w + w0 * a.w + w1 * c4.w + w2 * e4.w;
            *(float4*)(sH + m * HST + f) = r;
        }
    }
    __syncthreads();

    int ty = tid >> 4, tx = tid & 15;
    int nn = tx * 8;

    // init accumulators from gathered interp (+b1) in sH
    float acc[8][8];
    #pragma unroll
    for (int i = 0; i < 8; i++) {
        int r = ty + 16 * i;
        float4 v0 = *(const float4*)(sH + r * HST + nn);
        float4 v1 = *(const float4*)(sH + r * HST + nn + 4);
        acc[i][0] = v0.x; acc[i][1] = v0.y; acc[i][2] = v0.z; acc[i][3] = v0.w;
        acc[i][4] = v1.x; acc[i][5] = v1.y; acc[i][6] = v1.z; acc[i][7] = v1.w;
    }

    // GEMM1: A(128x64) @ W1b(64x128), k in chunks of 4 with float4 A loads
    #pragma unroll 1
    for (int kc = 0; kc < 64; kc += 4) {
        float4 wv[4][2];
        #pragma unroll
        for (int t = 0; t < 4; t++) {
            wv[t][0] = *(const float4*)(sW1b + (kc + t) * 128 + nn);
            wv[t][1] = *(const float4*)(sW1b + (kc + t) * 128 + nn + 4);
        }
        #pragma unroll
        for (int i = 0; i < 8; i++) {
            float4 a4 = *(const float4*)(sA + (ty + 16 * i) * AST + kc);
            #pragma unroll
            for (int c = 0; c < 4; c++) {
                acc[i][c]     = fmaf(a4.x, (&wv[0][0].x)[c], acc[i][c]);
                acc[i][c + 4] = fmaf(a4.x, (&wv[0][1].x)[c], acc[i][c + 4]);
                acc[i][c]     = fmaf(a4.y, (&wv[1][0].x)[c], acc[i][c]);
                acc[i][c + 4] = fmaf(a4.y, (&wv[1][1].x)[c], acc[i][c + 4]);
                acc[i][c]     = fmaf(a4.z, (&wv[2][0].x)[c], acc[i][c]);
                acc[i][c + 4] = fmaf(a4.z, (&wv[2][1].x)[c], acc[i][c + 4]);
                acc[i][c]     = fmaf(a4.w, (&wv[3][0].x)[c], acc[i][c]);
                acc[i][c + 4] = fmaf(a4.w, (&wv[3][1].x)[c], acc[i][c + 4]);
            }
        }
    }

    // relu -> sH (same cells this thread read/initialized: race-free)
    #pragma unroll
    for (int i = 0; i < 8; i++) {
        int r = ty + 16 * i;
        float4 v0, v1;
        v0.x = fmaxf(acc[i][0], 0.f); v0.y = fmaxf(acc[i][1], 0.f);
        v0.z = fmaxf(acc[i][2], 0.f); v0.w = fmaxf(acc[i][3], 0.f);
        v1.x = fmaxf(acc[i][4], 0.f); v1.y = fmaxf(acc[i][5], 0.f);
        v1.z = fmaxf(acc[i][6], 0.f); v1.w = fmaxf(acc[i][7], 0.f);
        *(float4*)(sH + r * HST + nn) = v0;
        *(float4*)(sH + r * HST + nn + 4) = v1;
    }
    __syncthreads();

    // GEMM2: H(128x128) @ W2(128x128), k in chunks of 4 with float4 H loads
    float4 b2a = *(const float4*)(sB2 + nn);
    float4 b2b = *(const float4*)(sB2 + nn + 4);
    float acc2[8][8];
    #pragma unroll
    for (int i = 0; i < 8; i++) {
        acc2[i][0] = b2a.x; acc2[i][1] = b2a.y; acc2[i][2] = b2a.z; acc2[i][3] = b2a.w;
        acc2[i][4] = b2b.x; acc2[i][5] = b2b.y; acc2[i][6] = b2b.z; acc2[i][7] = b2b.w;
    }
    #pragma unroll 1
    for (int kc = 0; kc < 128; kc += 4) {
        float4 wv[4][2];
        #pragma unroll
        for (int t = 0; t < 4; t++) {
            wv[t][0] = *(const float4*)(sW2 + (kc + t) * 128 + nn);
            wv[t][1] = *(const float4*)(sW2 + (kc + t) * 128 + nn + 4);
        }
        #pragma unroll
        for (int i = 0; i < 8; i++) {
            float4 h4 = *(const float4*)(sH + (ty + 16 * i) * HST + kc);
            #pragma unroll
            for (int c = 0; c < 4; c++) {
                acc2[i][c]     = fmaf(h4.x, (&wv[0][0].x)[c], acc2[i][c]);
                acc2[i][c + 4] = fmaf(h4.x, (&wv[0][1].x)[c], acc2[i][c + 4]);
                acc2[i][c]     = fmaf(h4.y, (&wv[1][0].x)[c], acc2[i][c]);
                acc2[i][c + 4] = fmaf(h4.y, (&wv[1][1].x)[c], acc2[i][c + 4]);
                acc2[i][c]     = fmaf(h4.z, (&wv[2][0].x)[c], acc2[i][c]);
                acc2[i][c + 4] = fmaf(h4.z, (&wv[2][1].x)[c], acc2[i][c + 4]);
                acc2[i][c]     = fmaf(h4.w, (&wv[3][0].x)[c], acc2[i][c]);
                acc2[i][c + 4] = fmaf(h4.w, (&wv[3][1].x)[c], acc2[i][c + 4]);
            }
        }
    }

    // relu -> global
    #pragma unroll
    for (int i = 0; i < 8; i++) {
        int g = g0 + ty + 16 * i;
        float4 v0, v1;
        v0.x = fmaxf(acc2[i][0], 0.f); v0.y = fmaxf(acc2[i][1], 0.f);
        v0.z = fmaxf(acc2[i][2], 0.f); v0.w = fmaxf(acc2[i][3], 0.f);
        v1.x = fmaxf(acc2[i][4], 0.f); v1.y = fmaxf(acc2[i][5], 0.f);
        v1.z = fmaxf(acc2[i][6], 0.f); v1.w = fmaxf(acc2[i][7], 0.f);
        *(float4*)(out + (size_t)g * F2 + nn) = v0;
        *(float4*)(out + (size_t)g * F2 + nn + 4) = v1;
    }
}

// ---------------------------------------------------------------------------
extern "C" void kernel_launch(void* const* d_in, const int* in_sizes, int n_in,
                              void* d_out, int out_size) {
    const float* in0 = (const float*)d_in[0];   // inputs0 (B, N1, 131)
    const float* in1 = (const float*)d_in[1];   // inputs1 (B, N2, 67)
    const float* W1  = (const float*)d_in[2];   // (192, 128)
    const float* b1  = (const float*)d_in[3];   // (128,)
    const float* W2  = (const float*)d_in[4];   // (128, 128)
    const float* b2  = (const float*)d_in[5];   // (128,)
    float* out = (float*)d_out;

    const int x_elems = BATCH * N2 * F2;                 // 8,388,608
    int write_xyz = (out_size >= x_elems + BATCH * N2 * 3) ? 1 : 0;

    const int mlp_smem = (16384 + 8192 + 128 * AST + 128 * HST + 256) * (int)sizeof(float);
    cudaFuncSetAttribute(mlp_kernel, cudaFuncAttributeMaxDynamicSharedMemorySize, mlp_smem);

    knn_part_kernel<<<dim3(N2 / 512, NSLICE, BATCH), 256>>>(in0, in1);
    pw_kernel<<<(BATCH * N1) / 8, 128>>>(in0, W1);
    knn_merge_kernel<<<(BATCH * N2) / 256, 256>>>(in0, in1, out + x_elems, write_xyz);
    mlp_kernel<<<(BATCH * N2) / 128, 256, mlp_smem>>>(in1, W1, b1, W2, b2, out);
}

// round 16
// speedup vs baseline: 2.2740x; 1.2232x over previous
#include <cuda_runtime.h>
#include <cuda_bf16.h>
#include <math_constants.h>
#include <cstdint>

#define BATCH 2
#define N1 4096
#define N2 32768
#define C1 128
#define C2 64
#define F1 128
#define F2 128
#define IN0S 131   // 3 + C1
#define IN1S 67    // 3 + C2
#define KEPS 1e-7f

#define HST 136    // sH fp32 row stride (floats)
#define ASTB 72    // bf16 row stride for A / W1bT (36 banks, ≡4 mod 32)
#define HSTB 136   // bf16 row stride for H / W2T  (68 banks, ≡4 mod 32)

#define NSLICE 4               // knn candidate-dim split
#define CPT (N1 / NSLICE)      // 1024 candidates per slice

// ---- mlp smem byte map ----------------------------------------------------
#define SH_B    0          // sH fp32: 128*136*4 = 69632   (aliased by H bf16)
#define HHI_B   0          // H hi bf16: 128*136*2 = 34816
#define HLO_B   34816      // H lo bf16: 34816
#define AHI_B   69632      // A hi bf16: 128*72*2 = 18432
#define ALO_B   88064
#define W1HI_B  106496     // W1b^T hi bf16 (n,k): 18432
#define W1LO_B  124928
#define W2HI_B  143360     // W2^T hi bf16 (n,k): 34816
#define W2LO_B  178176
#define B1_B    212992     // 128 floats
#define B2_B    213504     // 128 floats
#define MLP_SMEM_B 214016

// Scratch (static device globals: allocation-free)
__device__ float g_PW[BATCH * N1 * F1];          // points1 @ W1[0:128,:]
__device__ int   g_idx[BATCH * N2 * 3];
__device__ float g_w[BATCH * N2 * 3];
__device__ float g_pd[BATCH * N2 * NSLICE * 3];
__device__ int   g_pi[BATCH * N2 * NSLICE * 3];

#define TOP3_UPDATE(d, e0, e1, e2, i0, i1, i2, j)              \
    if ((d) < (e2)) {                                          \
        if ((d) < (e1)) {                                      \
            (e2) = (e1); (i2) = (i1);                          \
            if ((d) < (e0)) { (e1) = (e0); (i1) = (i0);        \
                              (e0) = (d);  (i0) = (j); }       \
            else            { (e1) = (d);  (i1) = (j); }       \
        } else { (e2) = (d); (i2) = (j); }                     \
    }

// bf16 warp MMA: D(16x8) += A(16x16,row) * B(16x8,col)  — base-target PTX
#define MMA_BF16(c, a0, a1, a2, a3, b0, b1)                                   \
    asm volatile(                                                             \
        "mma.sync.aligned.m16n8k16.row.col.f32.bf16.bf16.f32 "                \
        "{%0,%1,%2,%3}, {%4,%5,%6,%7}, {%8,%9}, {%0,%1,%2,%3};"               \
        : "+f"((c)[0]), "+f"((c)[1]), "+f"((c)[2]), "+f"((c)[3])              \
        : "r"(a0), "r"(a1), "r"(a2), "r"(a3), "r"(b0), "r"(b1))

__device__ __forceinline__ uint32_t pack_bf16_hi2(float x, float y,
                                                  uint32_t* lo) {
    __nv_bfloat16 hx = __float2bfloat16(x);
    __nv_bfloat16 hy = __float2bfloat16(y);
    __nv_bfloat16 lx = __float2bfloat16(x - __bfloat162float(hx));
    __nv_bfloat16 ly = __float2bfloat16(y - __bfloat162float(hy));
    *lo = (uint32_t)__bfloat16_as_ushort(lx)
        | ((uint32_t)__bfloat16_as_ushort(ly) << 16);
    return (uint32_t)__bfloat16_as_ushort(hx)
        | ((uint32_t)__bfloat16_as_ushort(hy) << 16);
}

// ---------------------------------------------------------------------------
// K0: PW = points1 @ W1[0:128,:]
// ---------------------------------------------------------------------------
__global__ void pw_kernel(const float* __restrict__ in0, const float* __restrict__ W1) {
    __shared__ float srow[8][128];
    int tid = threadIdx.x;
    long rowbase = (long)blockIdx.x * 8;
    #pragma unroll
    for (int r = 0; r < 8; r++)
        srow[r][tid] = in0[(rowbase + r) * IN0S + 3 + tid];
    __syncthreads();
    float acc[8];
    #pragma unroll
    for (int r = 0; r < 8; r++) acc[r] = 0.f;
    #pragma unroll 4
    for (int k = 0; k < 128; k++) {
        float w = __ldg(&W1[k * F1 + tid]);
        #pragma unroll
        for (int r = 0; r < 8; r++) acc[r] = fmaf(srow[r][k], w, acc[r]);
    }
    #pragma unroll
    for (int r = 0; r < 8; r++)
        g_PW[(rowbase + r) * F1 + tid] = acc[r];
}

// ---------------------------------------------------------------------------
// K1a: partial 3-NN (proven config: 2 queries/thread, NSLICE slices)
// ---------------------------------------------------------------------------
__global__ void knn_part_kernel(const float* __restrict__ in0,
                                const float* __restrict__ in1) {
    __shared__ float4 tile[CPT];
    int tid = threadIdx.x;
    int b  = blockIdx.z;
    int sl = blockIdx.y;
    int cs = sl * CPT;
    int qA = blockIdx.x * 512 + tid;
    int qB = qA + 256;
    int gA = b * N2 + qA;
    int gB = b * N2 + qB;

    const float* q = in1 + (size_t)gA * IN1S;
    float nAx = -2.f * q[0], nAy = -2.f * q[1], nAz = -2.f * q[2];
    q = in1 + (size_t)gB * IN1S;
    float nBx = -2.f * q[0], nBy = -2.f * q[1], nBz = -2.f * q[2];

    for (int s = tid; s < CPT; s += 256) {
        const float* p = in0 + (size_t)(b * N1 + cs + s) * IN0S;
        float px = p[0], py = p[1], pz = p[2];
        tile[s] = make_float4(px, py, pz, fmaf(px, px, fmaf(py, py, pz * pz)));
    }
    __syncthreads();

    float eA0 = CUDART_INF_F, eA1 = CUDART_INF_F, eA2 = CUDART_INF_F;
    float eB0 = CUDART_INF_F, eB1 = CUDART_INF_F, eB2 = CUDART_INF_F;
    int iA0 = 0, iA1 = 0, iA2 = 0, iB0 = 0, iB1 = 0, iB2 = 0;

    #pragma unroll 8
    for (int s = 0; s < CPT; s++) {
        float4 p = tile[s];
        float dA = fmaf(p.x, nAx, p.w);
        dA = fmaf(p.y, nAy, dA);
        dA = fmaf(p.z, nAz, dA);
        float dB = fmaf(p.x, nBx, p.w);
        dB = fmaf(p.y, nBy, dB);
        dB = fmaf(p.z, nBz, dB);
        int j = cs + s;
        TOP3_UPDATE(dA, eA0, eA1, eA2, iA0, iA1, iA2, j);
        TOP3_UPDATE(dB, eB0, eB1, eB2, iB0, iB1, iB2, j);
    }

    size_t oA = ((size_t)gA * NSLICE + sl) * 3;
    size_t oB = ((size_t)gB * NSLICE + sl) * 3;
    g_pd[oA + 0] = eA0; g_pd[oA + 1] = eA1; g_pd[oA + 2] = eA2;
    g_pi[oA + 0] = iA0; g_pi[oA + 1] = iA1; g_pi[oA + 2] = iA2;
    g_pd[oB + 0] = eB0; g_pd[oB + 1] = eB1; g_pd[oB + 2] = eB2;
    g_pi[oB + 0] = iB0; g_pi[oB + 1] = iB1; g_pi[oB + 2] = iB2;
}

// ---------------------------------------------------------------------------
// K1b: merge partials, exact-distance recompute, weights + xyz
// ---------------------------------------------------------------------------
__global__ void knn_merge_kernel(const float* __restrict__ in0,
                                 const float* __restrict__ in1,
                                 float* __restrict__ out_xyz, int write_xyz) {
    int g = blockIdx.x * 256 + threadIdx.x;
    int b = g / N2;

    float e0 = CUDART_INF_F, e1 = CUDART_INF_F, e2 = CUDART_INF_F;
    int i0 = 0, i1 = 0, i2 = 0;
    size_t base = (size_t)g * NSLICE * 3;
    #pragma unroll
    for (int t = 0; t < NSLICE * 3; t++) {
        float d = g_pd[base + t];
        int   j = g_pi[base + t];
        TOP3_UPDATE(d, e0, e1, e2, i0, i1, i2, j);
    }

    const float* q = in1 + (size_t)g * IN1S;
    float qx = q[0], qy = q[1], qz = q[2];

    const float* P = in0 + (size_t)(b * N1) * IN0S;
    const float* p = P + (size_t)i0 * IN0S;
    float dx = p[0] - qx, dy = p[1] - qy, dz = p[2] - qz;
    float d0 = fmaxf(fmaf(dx, dx, fmaf(dy, dy, dz * dz)), KEPS);
    p = P + (size_t)i1 * IN0S;
    dx = p[0] - qx; dy = p[1] - qy; dz = p[2] - qz;
    float d1 = fmaxf(fmaf(dx, dx, fmaf(dy, dy, dz * dz)), KEPS);
    p = P + (size_t)i2 * IN0S;
    dx = p[0] - qx; dy = p[1] - qy; dz = p[2] - qz;
    float d2 = fmaxf(fmaf(dx, dx, fmaf(dy, dy, dz * dz)), KEPS);

    float w0 = 1.f / d0, w1 = 1.f / d1, w2 = 1.f / d2;
    float inv = 1.f / (w0 + w1 + w2);
    g_idx[g * 3 + 0] = i0; g_idx[g * 3 + 1] = i1; g_idx[g * 3 + 2] = i2;
    g_w[g * 3 + 0] = w0 * inv; g_w[g * 3 + 1] = w1 * inv; g_w[g * 3 + 2] = w2 * inv;
    if (write_xyz) {
        out_xyz[(size_t)g * 3 + 0] = qx;
        out_xyz[(size_t)g * 3 + 1] = qy;
        out_xyz[(size_t)g * 3 + 2] = qz;
    }
}

// ---------------------------------------------------------------------------
// K2: fused MLP v6 — both GEMMs on mma.sync bf16 hi/lo (base-target PTX).
// 128-query tile, 256 threads (8 warps). Warp w owns output rows 16w..16w+15.
// A laid (m, k-contig); B laid as B^T (n, k-contig) -> all fragment loads are
// contiguous 32-bit LDS; padded strides make them bank-conflict-free.
// ---------------------------------------------------------------------------
__global__ void __launch_bounds__(256, 1)
mlp_kernel(const float* __restrict__ in1, const float* __restrict__ W1,
           const float* __restrict__ b1, const float* __restrict__ W2,
           const float* __restrict__ b2, float* __restrict__ out) {
    extern __shared__ __align__(16) char smc[];
    float* sH  = (float*)(smc + SH_B);
    float* sB1 = (float*)(smc + B1_B);
    float* sB2 = (float*)(smc + B2_B);
    unsigned short* sAhi = (unsigned short*)(smc + AHI_B);
    unsigned short* sAlo = (unsigned short*)(smc + ALO_B);
    unsigned short* sW1hi = (unsigned short*)(smc + W1HI_B);
    unsigned short* sW1lo = (unsigned short*)(smc + W1LO_B);
    unsigned short* sW2hi = (unsigned short*)(smc + W2HI_B);
    unsigned short* sW2lo = (unsigned short*)(smc + W2LO_B);
    unsigned short* sHhi = (unsigned short*)(smc + HHI_B);
    unsigned short* sHlo = (unsigned short*)(smc + HLO_B);

    int tid = threadIdx.x;
    int wid = tid >> 5, lane = tid & 31;
    int gq = lane >> 2, tg = lane & 3;       // quad row / thread-in-quad
    int g0 = blockIdx.x * 128;
    int bb = g0 / N2;

    // ---- prologue: bf16 hi/lo conversions into smem ----
    for (int idx = tid; idx < 8192; idx += 256) {        // A: (m=128, c=64)
        int m = idx >> 6, c = idx & 63;
        float v = in1[(size_t)(g0 + m) * IN1S + 3 + c];
        __nv_bfloat16 h = __float2bfloat16(v);
        __nv_bfloat16 l = __float2bfloat16(v - __bfloat162float(h));
        sAhi[m * ASTB + c] = __bfloat16_as_ushort(h);
        sAlo[m * ASTB + c] = __bfloat16_as_ushort(l);
    }
    for (int idx = tid; idx < 8192; idx += 256) {        // W1b^T: (n=128, k=64)
        int n = idx & 127, k = idx >> 7;
        float v = W1[(size_t)(C1 + k) * F1 + n];
        __nv_bfloat16 h = __float2bfloat16(v);
        __nv_bfloat16 l = __float2bfloat16(v - __bfloat162float(h));
        sW1hi[n * ASTB + k] = __bfloat16_as_ushort(h);
        sW1lo[n * ASTB + k] = __bfloat16_as_ushort(l);
    }
    for (int idx = tid; idx < 16384; idx += 256) {       // W2^T: (n=128, k=128)
        int n = idx & 127, k = idx >> 7;
        float v = W2[(size_t)k * F2 + n];
        __nv_bfloat16 h = __float2bfloat16(v);
        __nv_bfloat16 l = __float2bfloat16(v - __bfloat162float(h));
        sW2hi[n * HSTB + k] = __bfloat16_as_ushort(h);
        sW2lo[n * HSTB + k] = __bfloat16_as_ushort(l);
    }
    if (tid < 128) { sB1[tid] = b1[tid]; sB2[tid] = b2[tid]; }
    __syncthreads();

    // ---- gather interpolation (+b1) -> sH fp32 (2 threads per query row) ----
    {
        int m  = tid >> 1;
        int fo = (tid & 1) * 64;
        int g  = g0 + m;
        int j0 = g_idx[g * 3 + 0], j1 = g_idx[g * 3 + 1], j2 = g_idx[g * 3 + 2];
        float w0 = g_w[g * 3 + 0], w1 = g_w[g * 3 + 1], w2 = g_w[g * 3 + 2];
        const float* Pg = g_PW + (size_t)bb * N1 * F1;
        const float* p0 = Pg + (size_t)j0 * F1;
        const float* p1 = Pg + (size_t)j1 * F1;
        const float* p2 = Pg + (size_t)j2 * F1;
        #pragma unroll
        for (int u = 0; u < 64; u += 4) {
            int f = fo + u;
            float4 a  = *(const float4*)(p0 + f);
            float4 c4 = *(const float4*)(p1 + f);
            float4 e4 = *(const float4*)(p2 + f);
            float4 bv = *(const float4*)(sB1 + f);
            float4 r;
            r.x = bv.x + w0 * a.x + w1 * c4.x + w2 * e4.x;
            r.y = bv.y + w0 * a.y + w1 * c4.y + w2 * e4.y;
            r.z = bv.z + w0 * a.z + w1 * c4.z + w2 * e4.z;
            r.w = bv.w + w0 * a.w + w1 * c4.w + w2 * e4.w;
            *(float4*)(sH + m * HST + f) = r;
        }
    }
    __syncthreads();

    int r0 = wid * 16 + gq;                  // this thread's fragment rows r0, r0+8

    // ---- GEMM1 accum init from sH (interp + b1) ----
    float c[16][4];
    #pragma unroll
    for (int nt = 0; nt < 16; nt++) {
        int n0 = nt * 8 + 2 * tg;
        float2 v0 = *(const float2*)(sH + r0 * HST + n0);
        float2 v1 = *(const float2*)(sH + (r0 + 8) * HST + n0);
        c[nt][0] = v0.x; c[nt][1] = v0.y;
        c[nt][2] = v1.x; c[nt][3] = v1.y;
    }
    __syncthreads();   // all sH reads complete (region reused for H bf16)

    // ---- GEMM1: A(128x64) @ W1b(64x128) via HMMA, K=64 -> 4 k-steps ----
    #pragma unroll
    for (int ks = 0; ks < 4; ks++) {
        int ka = ks * 16 + 2 * tg;
        uint32_t ah0 = *(const uint32_t*)(sAhi + r0 * ASTB + ka);
        uint32_t ah1 = *(const uint32_t*)(sAhi + (r0 + 8) * ASTB + ka);
        uint32_t ah2 = *(const uint32_t*)(sAhi + r0 * ASTB + ka + 8);
        uint32_t ah3 = *(const uint32_t*)(sAhi + (r0 + 8) * ASTB + ka + 8);
        uint32_t al0 = *(const uint32_t*)(sAlo + r0 * ASTB + ka);
        uint32_t al1 = *(const uint32_t*)(sAlo + (r0 + 8) * ASTB + ka);
        uint32_t al2 = *(const uint32_t*)(sAlo + r0 * ASTB + ka + 8);
        uint32_t al3 = *(const uint32_t*)(sAlo + (r0 + 8) * ASTB + ka + 8);
        #pragma unroll
        for (int nt = 0; nt < 16; nt++) {
            int nr = nt * 8 + gq;
            uint32_t bh0 = *(const uint32_t*)(sW1hi + nr * ASTB + ka);
            uint32_t bh1 = *(const uint32_t*)(sW1hi + nr * ASTB + ka + 8);
            uint32_t bl0 = *(const uint32_t*)(sW1lo + nr * ASTB + ka);
            uint32_t bl1 = *(const uint32_t*)(sW1lo + nr * ASTB + ka + 8);
            MMA_BF16(c[nt], ah0, ah1, ah2, ah3, bh0, bh1);
            MMA_BF16(c[nt], ah0, ah1, ah2, ah3, bl0, bl1);
            MMA_BF16(c[nt], al0, al1, al2, al3, bh0, bh1);
        }
    }

    // ---- relu + hi/lo split -> H bf16 (aliases dead sH region) ----
    #pragma unroll
    for (int nt = 0; nt < 16; nt++) {
        int n0 = nt * 8 + 2 * tg;
        uint32_t lo;
        uint32_t hi = pack_bf16_hi2(fmaxf(c[nt][0], 0.f), fmaxf(c[nt][1], 0.f), &lo);
        *(uint32_t*)(sHhi + r0 * HSTB + n0) = hi;
        *(uint32_t*)(sHlo + r0 * HSTB + n0) = lo;
        hi = pack_bf16_hi2(fmaxf(c[nt][2], 0.f), fmaxf(c[nt][3], 0.f), &lo);
        *(uint32_t*)(sHhi + (r0 + 8) * HSTB + n0) = hi;
        *(uint32_t*)(sHlo + (r0 + 8) * HSTB + n0) = lo;
    }
    __syncthreads();

    // ---- GEMM2: H(128x128) @ W2(128x128) via HMMA, K=128 -> 8 k-steps ----
    #pragma unroll
    for (int nt = 0; nt < 16; nt++) {
        c[nt][0] = 0.f; c[nt][1] = 0.f; c[nt][2] = 0.f; c[nt][3] = 0.f;
    }
    #pragma unroll
    for (int ks = 0; ks < 8; ks++) {
        int ka = ks * 16 + 2 * tg;
        uint32_t ah0 = *(const uint32_t*)(sHhi + r0 * HSTB + ka);
        uint32_t ah1 = *(const uint32_t*)(sHhi + (r0 + 8) * HSTB + ka);
        uint32_t ah2 = *(const uint32_t*)(sHhi + r0 * HSTB + ka + 8);
        uint32_t ah3 = *(const uint32_t*)(sHhi + (r0 + 8) * HSTB + ka + 8);
        uint32_t al0 = *(const uint32_t*)(sHlo + r0 * HSTB + ka);
        uint32_t al1 = *(const uint32_t*)(sHlo + (r0 + 8) * HSTB + ka);
        uint32_t al2 = *(const uint32_t*)(sHlo + r0 * HSTB + ka + 8);
        uint32_t al3 = *(const uint32_t*)(sHlo + (r0 + 8) * HSTB + ka + 8);
        #pragma unroll
        for (int nt = 0; nt < 16; nt++) {
            int nr = nt * 8 + gq;
            uint32_t bh0 = *(const uint32_t*)(sW2hi + nr * HSTB + ka);
            uint32_t bh1 = *(const uint32_t*)(sW2hi + nr * HSTB + ka + 8);
            uint32_t bl0 = *(const uint32_t*)(sW2lo + nr * HSTB + ka);
            uint32_t bl1 = *(const uint32_t*)(sW2lo + nr * HSTB + ka + 8);
            MMA_BF16(c[nt], ah0, ah1, ah2, ah3, bh0, bh1);
            MMA_BF16(c[nt], ah0, ah1, ah2, ah3, bl0, bl1);
            MMA_BF16(c[nt], al0, al1, al2, al3, bh0, bh1);
        }
    }

    // ---- epilogue: +b2, relu, store ----
    #pragma unroll
    for (int nt = 0; nt < 16; nt++) {
        int n0 = nt * 8 + 2 * tg;
        float2 bv = *(const float2*)(sB2 + n0);
        float2 v0, v1;
        v0.x = fmaxf(c[nt][0] + bv.x, 0.f);
        v0.y = fmaxf(c[nt][1] + bv.y, 0.f);
        v1.x = fmaxf(c[nt][2] + bv.x, 0.f);
        v1.y = fmaxf(c[nt][3] + bv.y, 0.f);
        *(float2*)(out + (size_t)(g0 + r0) * F2 + n0) = v0;
        *(float2*)(out + (size_t)(g0 + r0 + 8) * F2 + n0) = v1;
    }
}

// ---------------------------------------------------------------------------
extern "C" void kernel_launch(void* const* d_in, const int* in_sizes, int n_in,
                              void* d_out, int out_size) {
    const float* in0 = (const float*)d_in[0];   // inputs0 (B, N1, 131)
    const float* in1 = (const float*)d_in[1];   // inputs1 (B, N2, 67)
    const float* W1  = (const float*)d_in[2];   // (192, 128)
    const float* b1  = (const float*)d_in[3];   // (128,)
    const float* W2  = (const float*)d_in[4];   // (128, 128)
    const float* b2  = (const float*)d_in[5];   // (128,)
    float* out = (float*)d_out;

    const int x_elems = BATCH * N2 * F2;                 // 8,388,608
    int write_xyz = (out_size >= x_elems + BATCH * N2 * 3) ? 1 : 0;

    cudaFuncSetAttribute(mlp_kernel, cudaFuncAttributeMaxDynamicSharedMemorySize,
                         MLP_SMEM_B);

    knn_part_kernel<<<dim3(N2 / 512, NSLICE, BATCH), 256>>>(in0, in1);
    pw_kernel<<<(BATCH * N1) / 8, 128>>>(in0, W1);
    knn_merge_kernel<<<(BATCH * N2) / 256, 256>>>(in0, in1, out + x_elems, write_xyz);
    mlp_kernel<<<(BATCH * N2) / 128, 256, MLP_SMEM_B>>>(in1, W1, b1, W2, b2, out);
}